// round 6
// baseline (speedup 1.0000x reference)
#include <cuda_runtime.h>
#include <math.h>

// Problem constants
#define B_TOT  16384
#define T_LEN  128
#define F_DIM  9
#define H_DIM  128
#define O_DIM  12
#define G_DIM  512     // 4*H
#define TILE_B 64
#define NTHREADS 256
#define KC     16      // k-chunk staged per step

typedef unsigned long long ull;

// ---------------- packed f32x2 helpers ----------------
__device__ __forceinline__ ull pk2(float x, float y) {
    ull r;
    asm("mov.b64 %0, {%1, %2};" : "=l"(r) : "f"(x), "f"(y));
    return r;
}
__device__ __forceinline__ void unpk2(ull v, float& lo, float& hi) {
    asm("mov.b64 {%0, %1}, %2;" : "=f"(lo), "=f"(hi) : "l"(v));
}
__device__ __forceinline__ ull fma2(ull a, ull b, ull c) {
    ull d;
    asm("fma.rn.f32x2 %0, %1, %2, %3;" : "=l"(d) : "l"(a), "l"(b), "l"(c));
    return d;
}

// ---------------- pointwise gate math ----------------
__device__ __forceinline__ float sigf(float x) {
    return __fdividef(1.0f, 1.0f + __expf(-x));
}
__device__ __forceinline__ float tanhfast(float x) {
    float xc = fminf(fmaxf(x, -15.0f), 15.0f);
    float e = __expf(2.0f * xc);
    return __fdividef(e - 1.0f, e + 1.0f);
}

// ---------------- precomputed folded weights ----------------
// Weff = Wih0 @ W_in  -> stored transposed [9][512]
// beff = Wih0 @ b_in + bih0 + bhh0 ; bias1 = bih1 + bhh1
__device__ float g_WeffT[F_DIM * G_DIM];
__device__ float g_beff[G_DIM];
__device__ float g_bias1[G_DIM];

__global__ void precompute_kernel(const float* __restrict__ Wih0,
                                  const float* __restrict__ W_in,
                                  const float* __restrict__ b_in,
                                  const float* __restrict__ bih0,
                                  const float* __restrict__ bhh0,
                                  const float* __restrict__ bih1,
                                  const float* __restrict__ bhh1) {
    int j = threadIdx.x;  // 0..511
    float acc[F_DIM];
#pragma unroll
    for (int f = 0; f < F_DIM; f++) acc[f] = 0.0f;
    float bacc = 0.0f;
    for (int k = 0; k < H_DIM; k++) {
        float w = Wih0[j * H_DIM + k];
        bacc += w * b_in[k];
#pragma unroll
        for (int f = 0; f < F_DIM; f++) acc[f] += w * W_in[k * F_DIM + f];
    }
#pragma unroll
    for (int f = 0; f < F_DIM; f++) g_WeffT[f * G_DIM + j] = acc[f];
    g_beff[j] = bacc + bih0[j] + bhh0[j];
    g_bias1[j] = bih1[j] + bhh1[j];
}

// ---------------- main kernel helpers ----------------
__device__ __forceinline__ void init_acc(const float* sBias, int u0, ull (&acc)[4][2][8]) {
#pragma unroll
    for (int g = 0; g < 4; g++) {
#pragma unroll
        for (int up = 0; up < 2; up++) {
            ull b = *(const ull*)(sBias + g * H_DIM + u0 + 2 * up);
#pragma unroll
            for (int r = 0; r < 8; r++) acc[g][up][r] = b;
        }
    }
}

// Inner GEMM: acc[g][up][r] += S[r][k] * W[j][k] over k, j = g*128 + u0 + {0..3}
// Wt is transposed staging: Wt[k*512 + j]. S reads are warp-uniform broadcasts.
__device__ __forceinline__ void gemm_tile(const float* __restrict__ Sp, int sstride,
                                          const float* __restrict__ Wt, int nk,
                                          int u0, ull (&acc)[4][2][8]) {
#pragma unroll 4
    for (int k = 0; k < nk; k++) {
        ull hp[8];
#pragma unroll
        for (int r = 0; r < 8; r++) {
            float hv = Sp[r * sstride + k];
            hp[r] = pk2(hv, hv);
        }
#pragma unroll
        for (int g = 0; g < 4; g++) {
            float4 w4 = *(const float4*)(Wt + k * G_DIM + g * H_DIM + u0);
            ull w01 = pk2(w4.x, w4.y);
            ull w23 = pk2(w4.z, w4.w);
#pragma unroll
            for (int r = 0; r < 8; r++) {
                acc[g][0][r] = fma2(w01, hp[r], acc[g][0][r]);
                acc[g][1][r] = fma2(w23, hp[r], acc[g][1][r]);
            }
        }
    }
}

__device__ __forceinline__ void prefetch_chunk(int cc,
                                               const float* __restrict__ Whh0,
                                               const float* __restrict__ Wih1,
                                               const float* __restrict__ Whh1,
                                               int j0, int j1,
                                               float4 (&ra)[4], float4 (&rb)[4]) {
    const float* src = (cc < 8) ? Whh0 : ((cc < 16) ? Wih1 : Whh1);
    int k0 = (cc & 7) * KC;
    const float4* p0 = (const float4*)(src + (size_t)j0 * H_DIM + k0);
    const float4* p1 = (const float4*)(src + (size_t)j1 * H_DIM + k0);
#pragma unroll
    for (int i = 0; i < 4; i++) ra[i] = p0[i];
#pragma unroll
    for (int i = 0; i < 4; i++) rb[i] = p1[i];
}

__device__ __forceinline__ void store_chunk(float* sWst, int j0, int j1,
                                            const float4 (&ra)[4], const float4 (&rb)[4]) {
#pragma unroll
    for (int i = 0; i < 4; i++) {
        sWst[(i * 4 + 0) * G_DIM + j0] = ra[i].x;
        sWst[(i * 4 + 1) * G_DIM + j0] = ra[i].y;
        sWst[(i * 4 + 2) * G_DIM + j0] = ra[i].z;
        sWst[(i * 4 + 3) * G_DIM + j0] = ra[i].w;
        sWst[(i * 4 + 0) * G_DIM + j1] = rb[i].x;
        sWst[(i * 4 + 1) * G_DIM + j1] = rb[i].y;
        sWst[(i * 4 + 2) * G_DIM + j1] = rb[i].z;
        sWst[(i * 4 + 3) * G_DIM + j1] = rb[i].w;
    }
}

__device__ __forceinline__ void cell_update(ull (&acc)[4][2][8], float* sC, float* sH,
                                            int r0, int u0) {
#pragma unroll
    for (int r = 0; r < 8; r++) {
        float vi[4], vf[4], vg[4], vo[4];
        unpk2(acc[0][0][r], vi[0], vi[1]); unpk2(acc[0][1][r], vi[2], vi[3]);
        unpk2(acc[1][0][r], vf[0], vf[1]); unpk2(acc[1][1][r], vf[2], vf[3]);
        unpk2(acc[2][0][r], vg[0], vg[1]); unpk2(acc[2][1][r], vg[2], vg[3]);
        unpk2(acc[3][0][r], vo[0], vo[1]); unpk2(acc[3][1][r], vo[2], vo[3]);
        float* cp = sC + (r0 + r) * H_DIM + u0;
        float4 c4 = *(float4*)cp;
        float co[4] = {c4.x, c4.y, c4.z, c4.w};
        float cn[4], hn[4];
#pragma unroll
        for (int u = 0; u < 4; u++) {
            float gi = sigf(vi[u]);
            float gf = sigf(vf[u]);
            float gg = tanhfast(vg[u]);
            float go = sigf(vo[u]);
            float c_new = gf * co[u] + gi * gg;
            cn[u] = c_new;
            hn[u] = go * tanhfast(c_new);
        }
        *(float4*)cp = make_float4(cn[0], cn[1], cn[2], cn[3]);
        *(float4*)(sH + (r0 + r) * H_DIM + u0) = make_float4(hn[0], hn[1], hn[2], hn[3]);
    }
}

// ---------------- main persistent-tile LSTM kernel ----------------
// grid = 256 CTAs x 256 threads, each CTA owns 64 batch rows for all 128 steps.
__global__ void __launch_bounds__(NTHREADS, 1)
lstm_main(const float* __restrict__ x,
          const float* __restrict__ Whh0,
          const float* __restrict__ Wih1,
          const float* __restrict__ Whh1,
          const float* __restrict__ W_out,
          const float* __restrict__ b_out,
          float* __restrict__ out) {
    extern __shared__ float smem[];
    // shared partitions (floats)
    float* sXs    = smem;                 // 64*12  = 768
    float* sH0    = sXs + 768;            // 8192
    float* sH1    = sH0 + 8192;           // 8192
    float* sC0    = sH1 + 8192;           // 8192
    float* sC1    = sC0 + 8192;           // 8192
    float* sWst   = sC1 + 8192;           // 16*512 = 8192
    float* sWeffT = sWst + 8192;          // 9*512  = 4608
    float* sBeff  = sWeffT + 4608;        // 512
    float* sBias1 = sBeff + 512;          // 512

    const int tid  = threadIdx.x;
    const int lane = tid & 31;
    const int warp = tid >> 5;
    const int u0 = lane * 4;    // 4 units per thread
    const int r0 = warp * 8;    // 8 rows per thread
    const int b0 = blockIdx.x * TILE_B;
    const int j0 = tid, j1 = tid + 256;

    // init states + resident small weights
    for (int idx = tid; idx < 4 * 8192; idx += NTHREADS) sH0[idx] = 0.0f;  // H0,H1,C0,C1 contiguous
    for (int idx = tid; idx < F_DIM * G_DIM; idx += NTHREADS) sWeffT[idx] = g_WeffT[idx];
    for (int idx = tid; idx < G_DIM; idx += NTHREADS) { sBeff[idx] = g_beff[idx]; sBias1[idx] = g_bias1[idx]; }
    __syncthreads();

    float4 ra[4], rb[4];
    prefetch_chunk(0, Whh0, Wih1, Whh1, j0, j1, ra, rb);

    for (int t = 0; t < T_LEN; t++) {
        // load x tile for this timestep: x[b][t][0..8]
        for (int idx = tid; idx < TILE_B * F_DIM; idx += NTHREADS) {
            int r = idx / F_DIM, f = idx - r * F_DIM;
            sXs[r * 12 + f] = x[(size_t)(b0 + r) * (T_LEN * F_DIM) + t * F_DIM + f];
        }
        __syncthreads();

        // ---- layer 0 ----
        ull acc[4][2][8];
        init_acc(sBeff, u0, acc);
        gemm_tile(&sXs[r0 * 12], 12, sWeffT, F_DIM, u0, acc);          // folded x-part, K=9
        for (int c = 0; c < 8; c++) {                                   // h0 part, K=128
            __syncthreads();
            store_chunk(sWst, j0, j1, ra, rb);
            prefetch_chunk(c + 1, Whh0, Wih1, Whh1, j0, j1, ra, rb);
            __syncthreads();
            gemm_tile(&sH0[r0 * H_DIM + c * KC], H_DIM, sWst, KC, u0, acc);
        }
        __syncthreads();
        cell_update(acc, sC0, sH0, r0, u0);
        __syncthreads();

        // ---- layer 1 ----
        init_acc(sBias1, u0, acc);
        for (int c = 8; c < 24; c++) {                                  // Wih1 then Whh1, K=256
            __syncthreads();
            store_chunk(sWst, j0, j1, ra, rb);
            prefetch_chunk((c + 1) % 24, Whh0, Wih1, Whh1, j0, j1, ra, rb);
            __syncthreads();
            const float* S = (c < 16) ? sH0 : sH1;
            gemm_tile(&S[r0 * H_DIM + (c & 7) * KC], H_DIM, sWst, KC, u0, acc);
        }
        __syncthreads();
        cell_update(acc, sC1, sH1, r0, u0);
        __syncthreads();
    }

    // ---- epilogue: logits + softmax on last h1 ----
    if (tid < TILE_B) {
        int r = tid;
        const float* hr = &sH1[r * H_DIM];
        float lg[O_DIM];
#pragma unroll
        for (int o = 0; o < O_DIM; o++) {
            float s = b_out[o];
            for (int k = 0; k < H_DIM; k++) s += hr[k] * W_out[o * H_DIM + k];
            lg[o] = s;
        }
        float m = lg[0];
#pragma unroll
        for (int o = 1; o < O_DIM; o++) m = fmaxf(m, lg[o]);
        float sum = 0.0f;
#pragma unroll
        for (int o = 0; o < O_DIM; o++) { lg[o] = __expf(lg[o] - m); sum += lg[o]; }
        float inv = __fdividef(1.0f, sum);
#pragma unroll
        for (int o = 0; o < O_DIM; o++) out[(size_t)(b0 + r) * O_DIM + o] = lg[o] * inv;
    }
}

// ---------------- launch ----------------
extern "C" void kernel_launch(void* const* d_in, const int* in_sizes, int n_in,
                              void* d_out, int out_size) {
    (void)in_sizes; (void)n_in; (void)out_size;
    const float* x     = (const float*)d_in[0];
    const float* W_in  = (const float*)d_in[1];
    const float* b_in  = (const float*)d_in[2];
    const float* Wih0  = (const float*)d_in[3];
    const float* Whh0  = (const float*)d_in[4];
    const float* bih0  = (const float*)d_in[5];
    const float* bhh0  = (const float*)d_in[6];
    const float* Wih1  = (const float*)d_in[7];
    const float* Whh1  = (const float*)d_in[8];
    const float* bih1  = (const float*)d_in[9];
    const float* bhh1  = (const float*)d_in[10];
    const float* W_out = (const float*)d_in[11];
    const float* b_out = (const float*)d_in[12];
    float* out = (float*)d_out;

    const size_t smem_bytes = (size_t)(768 + 8192 * 5 + 4608 + 512 + 512) * sizeof(float); // 189440
    cudaFuncSetAttribute(lstm_main, cudaFuncAttributeMaxDynamicSharedMemorySize, (int)smem_bytes);

    precompute_kernel<<<1, G_DIM>>>(Wih0, W_in, b_in, bih0, bhh0, bih1, bhh1);
    lstm_main<<<B_TOT / TILE_B, NTHREADS, smem_bytes>>>(x, Whh0, Wih1, Whh1, W_out, b_out, out);
}